// round 13
// baseline (speedup 1.0000x reference)
#include <cuda_runtime.h>
#include <math.h>

// Problem constants
#define BB 64
#define JJ 42
#define PP 16384
#define JG 3            // joint groups
#define JT 14           // joints per group (JG*JT == JJ)
#define PC 4            // P chunks
#define PPB (PP/PC)     // 4096 points per block
#define THREADS 256
#define PPT (PPB/THREADS)   // 16 points per thread
#define NWARP (THREADS/32)
#define GRID (BB*JG*PC)     // 768 blocks
#define NBJ (BB*JJ)         // 2688

// Scratch: per-(b,j) partial min-squared-distance, one slot per P-chunk.
__device__ float g_partial[NBJ * PC];
__device__ unsigned int g_count;   // zero at load; last block resets each call

// X-macro over the 14 joints: fully-scalar named variables (no arrays ->
// nothing for ptxas to demote to local memory).
#define FOR_J(X) X(0) X(1) X(2) X(3) X(4) X(5) X(6) X(7) X(8) X(9) X(10) X(11) X(12) X(13)

__global__ __launch_bounds__(THREADS, 1) void sdl_fused_kernel(
    const float* __restrict__ pred,   // [B,J,3]
    const float* __restrict__ pts,    // [B,P,3]
    const float* __restrict__ gt,     // [B,J]
    float* __restrict__ out)
{
    const int blk = blockIdx.x;
    const int pc = blk % PC;
    const int jg = (blk / PC) % JG;
    const int b  = blk / (PC * JG);
    const int t  = threadIdx.x;

    const float* jp = pred + (size_t)(b * JJ + jg * JT) * 3;

    // 70 named scalars: mx/my/mz/acc per joint (a2 folded in epilogue).
#define DECL(n) float mx##n, my##n, mz##n, acc##n;
    FOR_J(DECL)
#undef DECL

#define INIT(n) { float ax = jp[3*n+0], ay = jp[3*n+1], az = jp[3*n+2]; \
                  mx##n = -2.0f*ax; my##n = -2.0f*ay; mz##n = -2.0f*az; \
                  acc##n = 3.0e38f; }
    FOR_J(INIT)
#undef INIT

    // Points for this (b, pc): 4096 points via aligned float4 loads.
    const float4* p4 = (const float4*)(pts + ((size_t)b * PP + (size_t)pc * PPB) * 3);

#pragma unroll 1
    for (int it = 0; it < PPT / 4; it++) {
        const int f4 = it * (THREADS * 3) + t * 3;
        float4 A  = p4[f4 + 0];
        float4 Bv = p4[f4 + 1];
        float4 C  = p4[f4 + 2];

#pragma unroll
        for (int q = 0; q < 4; q++) {
            float px, py, pz;
            if (q == 0)      { px = A.x;  py = A.y;  pz = A.z;  }
            else if (q == 1) { px = A.w;  py = Bv.x; pz = Bv.y; }
            else if (q == 2) { px = Bv.z; py = Bv.w; pz = C.x;  }
            else             { px = C.y;  py = C.z;  pz = C.w;  }
            float b2 = fmaf(pz, pz, fmaf(py, py, px * px));
#define UPD(n) { float tq = fmaf(mx##n, px, fmaf(my##n, py, fmaf(mz##n, pz, b2))); \
                 acc##n = fminf(acc##n, tq); }
            FOR_J(UPD)
#undef UPD
        }
    }

    // Epilogue: fold |a|^2, warp min-reduce, deposit in smem per joint.
    __shared__ float smin[NWARP][JT];
    const int w = t >> 5, l = t & 31;

#define FIN(n) { float ax = jp[3*n+0], ay = jp[3*n+1], az = jp[3*n+2]; \
                 float v = acc##n + fmaf(az, az, fmaf(ay, ay, ax*ax)); \
                 v = fminf(v, __shfl_xor_sync(0xFFFFFFFFu, v, 16)); \
                 v = fminf(v, __shfl_xor_sync(0xFFFFFFFFu, v, 8));  \
                 v = fminf(v, __shfl_xor_sync(0xFFFFFFFFu, v, 4));  \
                 v = fminf(v, __shfl_xor_sync(0xFFFFFFFFu, v, 2));  \
                 v = fminf(v, __shfl_xor_sync(0xFFFFFFFFu, v, 1));  \
                 if (l == 0) smin[w][n] = v; }
    FOR_J(FIN)
#undef FIN

    __syncthreads();

    if (t < JT) {
        float v = smin[0][t];
#pragma unroll
        for (int wi = 1; wi < NWARP; wi++) v = fminf(v, smin[wi][t]);
        g_partial[(size_t)(b * JJ + jg * JT + t) * PC + pc] = v;
    }

    // ---- last-block finalize (fused MSE) ----
    __threadfence();
    __syncthreads();
    __shared__ unsigned s_last;
    if (t == 0) {
        unsigned c = atomicAdd(&g_count, 1u);
        s_last = (c == (unsigned)(GRID - 1)) ? 1u : 0u;
    }
    __syncthreads();
    if (s_last == 0u) return;

    // Last block: all partials globally visible (L2-hot).
    float s = 0.0f;
    const float4* gp = (const float4*)g_partial;
#pragma unroll 1
    for (int i = t; i < NBJ; i += THREADS) {
        float4 v = __ldcg(gp + i);
        float m = fminf(fminf(v.x, v.y), fminf(v.z, v.w));
        m = fmaxf(m, 0.0f);
        float d = sqrtf(m) - gt[i];
        s = fmaf(d, d, s);
    }
    // Deterministic fixed-order reduction.
    s += __shfl_xor_sync(0xFFFFFFFFu, s, 16);
    s += __shfl_xor_sync(0xFFFFFFFFu, s, 8);
    s += __shfl_xor_sync(0xFFFFFFFFu, s, 4);
    s += __shfl_xor_sync(0xFFFFFFFFu, s, 2);
    s += __shfl_xor_sync(0xFFFFFFFFu, s, 1);
    __shared__ float ssum[NWARP];
    if (l == 0) ssum[w] = s;
    __syncthreads();
    if (t == 0) {
        float tot = ssum[0];
#pragma unroll
        for (int wi = 1; wi < NWARP; wi++) tot += ssum[wi];
        out[0] = tot / (float)NBJ;
        g_count = 0;   // reset for next graph replay
    }
}

extern "C" void kernel_launch(void* const* d_in, const int* in_sizes, int n_in,
                              void* d_out, int out_size) {
    (void)in_sizes; (void)n_in; (void)out_size;
    const float* pred = (const float*)d_in[0];   // [64,42,3]
    const float* pts  = (const float*)d_in[1];   // [64,16384,3]
    const float* gt   = (const float*)d_in[2];   // [64,42]
    float* out = (float*)d_out;

    sdl_fused_kernel<<<GRID, THREADS>>>(pred, pts, gt, out);
}

// round 14
// speedup vs baseline: 1.1633x; 1.1633x over previous
#include <cuda_runtime.h>
#include <math.h>

// Problem constants
#define BB 64
#define JJ 42
#define PP 16384
#define JG 3            // joint groups
#define JT 14           // joints per group (JG*JT == JJ)
#define PC 4            // P chunks
#define PPB (PP/PC)     // 4096 points per block
#define THREADS 256
#define PPT (PPB/THREADS)   // 16 points per thread
#define NWARP (THREADS/32)
#define GRID (BB*JG*PC)     // 768 blocks
#define NBJ (BB*JJ)         // 2688

// Scratch: per-(b,j) partial min-squared-distance, one slot per P-chunk.
__device__ float g_partial[NBJ * PC];
__device__ unsigned int g_count;   // zero at load; last block resets each call

// X-macro over the 14 joints: fully-scalar named variables (no arrays ->
// nothing for ptxas to demote to local memory).
#define FOR_J(X) X(0) X(1) X(2) X(3) X(4) X(5) X(6) X(7) X(8) X(9) X(10) X(11) X(12) X(13)

// NOTE: no __launch_bounds__ — R12 proved ptxas's default register heuristic
// gives the right occupancy/register balance for this scalarized loop;
// R13 proved min-blocks=1 (151 regs, occ 12%) exposes load latency.
__global__ void sdl_fused_kernel(
    const float* __restrict__ pred,   // [B,J,3]
    const float* __restrict__ pts,    // [B,P,3]
    const float* __restrict__ gt,     // [B,J]
    float* __restrict__ out)
{
    const int blk = blockIdx.x;
    const int pc = blk % PC;
    const int jg = (blk / PC) % JG;
    const int b  = blk / (PC * JG);
    const int t  = threadIdx.x;

    const float* jp = pred + (size_t)(b * JJ + jg * JT) * 3;

    // 70 named scalars: mx/my/mz/acc per joint (a2 folded in epilogue).
#define DECL(n) float mx##n, my##n, mz##n, acc##n;
    FOR_J(DECL)
#undef DECL

#define INIT(n) { float ax = jp[3*n+0], ay = jp[3*n+1], az = jp[3*n+2]; \
                  mx##n = -2.0f*ax; my##n = -2.0f*ay; mz##n = -2.0f*az; \
                  acc##n = 3.0e38f; }
    FOR_J(INIT)
#undef INIT

    // Points for this (b, pc): 4096 points via aligned float4 loads.
    const float4* p4 = (const float4*)(pts + ((size_t)b * PP + (size_t)pc * PPB) * 3);

#pragma unroll 1
    for (int it = 0; it < PPT / 4; it++) {
        const int f4 = it * (THREADS * 3) + t * 3;
        float4 A  = p4[f4 + 0];
        float4 Bv = p4[f4 + 1];
        float4 C  = p4[f4 + 2];

#pragma unroll
        for (int q = 0; q < 4; q++) {
            float px, py, pz;
            if (q == 0)      { px = A.x;  py = A.y;  pz = A.z;  }
            else if (q == 1) { px = A.w;  py = Bv.x; pz = Bv.y; }
            else if (q == 2) { px = Bv.z; py = Bv.w; pz = C.x;  }
            else             { px = C.y;  py = C.z;  pz = C.w;  }
            float b2 = fmaf(pz, pz, fmaf(py, py, px * px));
#define UPD(n) { float tq = fmaf(mx##n, px, fmaf(my##n, py, fmaf(mz##n, pz, b2))); \
                 acc##n = fminf(acc##n, tq); }
            FOR_J(UPD)
#undef UPD
        }
    }

    // Epilogue: fold |a|^2, warp min-reduce, deposit in smem per joint.
    __shared__ float smin[NWARP][JT];
    const int w = t >> 5, l = t & 31;

#define FIN(n) { float ax = jp[3*n+0], ay = jp[3*n+1], az = jp[3*n+2]; \
                 float v = acc##n + fmaf(az, az, fmaf(ay, ay, ax*ax)); \
                 v = fminf(v, __shfl_xor_sync(0xFFFFFFFFu, v, 16)); \
                 v = fminf(v, __shfl_xor_sync(0xFFFFFFFFu, v, 8));  \
                 v = fminf(v, __shfl_xor_sync(0xFFFFFFFFu, v, 4));  \
                 v = fminf(v, __shfl_xor_sync(0xFFFFFFFFu, v, 2));  \
                 v = fminf(v, __shfl_xor_sync(0xFFFFFFFFu, v, 1));  \
                 if (l == 0) smin[w][n] = v; }
    FOR_J(FIN)
#undef FIN

    __syncthreads();

    if (t < JT) {
        float v = smin[0][t];
#pragma unroll
        for (int wi = 1; wi < NWARP; wi++) v = fminf(v, smin[wi][t]);
        g_partial[(size_t)(b * JJ + jg * JT + t) * PC + pc] = v;
    }

    // ---- last-block finalize (fused MSE) ----
    __threadfence();
    __syncthreads();
    __shared__ unsigned s_last;
    if (t == 0) {
        unsigned c = atomicAdd(&g_count, 1u);
        s_last = (c == (unsigned)(GRID - 1)) ? 1u : 0u;
    }
    __syncthreads();
    if (s_last == 0u) return;

    // Last block: all partials globally visible (L2-hot).
    float s = 0.0f;
    const float4* gp = (const float4*)g_partial;
#pragma unroll 1
    for (int i = t; i < NBJ; i += THREADS) {
        float4 v = __ldcg(gp + i);
        float m = fminf(fminf(v.x, v.y), fminf(v.z, v.w));
        m = fmaxf(m, 0.0f);
        float d = sqrtf(m) - gt[i];
        s = fmaf(d, d, s);
    }
    // Deterministic fixed-order reduction.
    s += __shfl_xor_sync(0xFFFFFFFFu, s, 16);
    s += __shfl_xor_sync(0xFFFFFFFFu, s, 8);
    s += __shfl_xor_sync(0xFFFFFFFFu, s, 4);
    s += __shfl_xor_sync(0xFFFFFFFFu, s, 2);
    s += __shfl_xor_sync(0xFFFFFFFFu, s, 1);
    __shared__ float ssum[NWARP];
    if (l == 0) ssum[w] = s;
    __syncthreads();
    if (t == 0) {
        float tot = ssum[0];
#pragma unroll
        for (int wi = 1; wi < NWARP; wi++) tot += ssum[wi];
        out[0] = tot / (float)NBJ;
        g_count = 0;   // reset for next graph replay
    }
}

extern "C" void kernel_launch(void* const* d_in, const int* in_sizes, int n_in,
                              void* d_out, int out_size) {
    (void)in_sizes; (void)n_in; (void)out_size;
    const float* pred = (const float*)d_in[0];   // [64,42,3]
    const float* pts  = (const float*)d_in[1];   // [64,16384,3]
    const float* gt   = (const float*)d_in[2];   // [64,42]
    float* out = (float*)d_out;

    sdl_fused_kernel<<<GRID, THREADS>>>(pred, pts, gt, out);
}

// round 15
// speedup vs baseline: 1.2545x; 1.0784x over previous
#include <cuda_runtime.h>
#include <math.h>

// Problem constants
#define BB 64
#define JJ 42
#define PP 16384
#define JG 3            // joint groups
#define JT 14           // joints per group (JG*JT == JJ)
#define PC 4            // P chunks
#define PPB (PP/PC)     // 4096 points per block
#define THREADS 256
#define PPT (PPB/THREADS)   // 16 points per thread
#define NWARP (THREADS/32)
#define GRID (BB*JG*PC)     // 768 blocks
#define NBJ (BB*JJ)         // 2688
#define MSE_BLOCKS 21       // 21 * 128 = 2688
#define MSE_THREADS 128

// Scratch: per-(b,j) partial min-squared-distance, one slot per P-chunk.
__device__ float g_partial[NBJ * PC];
__device__ float g_bsum[MSE_BLOCKS];
__device__ unsigned int g_mse_count;   // zero at load; last block resets

// X-macro over the 14 joints: fully-scalar named variables (no arrays ->
// nothing for ptxas to demote to local memory).
#define FOR_J(X) X(0) X(1) X(2) X(3) X(4) X(5) X(6) X(7) X(8) X(9) X(10) X(11) X(12) X(13)

// No __launch_bounds__: default heuristic gives ~128 regs / 2 blocks/SM (R14),
// which fits the ~112-reg live set including the prefetch buffer.
__global__ void sdl_min_kernel(
    const float* __restrict__ pred,   // [B,J,3]
    const float* __restrict__ pts)    // [B,P,3]
{
    const int blk = blockIdx.x;
    const int pc = blk % PC;
    const int jg = (blk / PC) % JG;
    const int b  = blk / (PC * JG);
    const int t  = threadIdx.x;

    const float* jp = pred + (size_t)(b * JJ + jg * JT) * 3;

#define DECL(n) float mx##n, my##n, mz##n, acc##n;
    FOR_J(DECL)
#undef DECL

#define INIT(n) { float ax = jp[3*n+0], ay = jp[3*n+1], az = jp[3*n+2]; \
                  mx##n = -2.0f*ax; my##n = -2.0f*ay; mz##n = -2.0f*az; \
                  acc##n = 3.0e38f; }
    FOR_J(INIT)
#undef INIT

    const float4* p4 = (const float4*)(pts + ((size_t)b * PP + (size_t)pc * PPB) * 3);

    // Prime the register double-buffer with iteration 0's loads.
    float4 A  = p4[t * 3 + 0];
    float4 Bv = p4[t * 3 + 1];
    float4 C  = p4[t * 3 + 2];

#pragma unroll 1
    for (int it = 0; it < PPT / 4; it++) {
        // Prefetch next iteration's 3 float4 before consuming current ones.
        float4 An, Bn, Cn;
        if (it + 1 < PPT / 4) {
            const int f4 = (it + 1) * (THREADS * 3) + t * 3;
            An = p4[f4 + 0];
            Bn = p4[f4 + 1];
            Cn = p4[f4 + 2];
        }

#pragma unroll
        for (int q = 0; q < 4; q++) {
            float px, py, pz;
            if (q == 0)      { px = A.x;  py = A.y;  pz = A.z;  }
            else if (q == 1) { px = A.w;  py = Bv.x; pz = Bv.y; }
            else if (q == 2) { px = Bv.z; py = Bv.w; pz = C.x;  }
            else             { px = C.y;  py = C.z;  pz = C.w;  }
            float b2 = fmaf(pz, pz, fmaf(py, py, px * px));
#define UPD(n) { float tq = fmaf(mx##n, px, fmaf(my##n, py, fmaf(mz##n, pz, b2))); \
                 acc##n = fminf(acc##n, tq); }
            FOR_J(UPD)
#undef UPD
        }

        A = An; Bv = Bn; C = Cn;
    }

    // Epilogue: fold |a|^2, warp min-reduce, deposit in smem per joint.
    __shared__ float smin[NWARP][JT];
    const int w = t >> 5, l = t & 31;

#define FIN(n) { float ax = jp[3*n+0], ay = jp[3*n+1], az = jp[3*n+2]; \
                 float v = acc##n + fmaf(az, az, fmaf(ay, ay, ax*ax)); \
                 v = fminf(v, __shfl_xor_sync(0xFFFFFFFFu, v, 16)); \
                 v = fminf(v, __shfl_xor_sync(0xFFFFFFFFu, v, 8));  \
                 v = fminf(v, __shfl_xor_sync(0xFFFFFFFFu, v, 4));  \
                 v = fminf(v, __shfl_xor_sync(0xFFFFFFFFu, v, 2));  \
                 v = fminf(v, __shfl_xor_sync(0xFFFFFFFFu, v, 1));  \
                 if (l == 0) smin[w][n] = v; }
    FOR_J(FIN)
#undef FIN

    __syncthreads();

    if (t < JT) {
        float v = smin[0][t];
#pragma unroll
        for (int wi = 1; wi < NWARP; wi++) v = fminf(v, smin[wi][t]);
        g_partial[(size_t)(b * JJ + jg * JT + t) * PC + pc] = v;
    }
}

// Finalize: 21 blocks x 128 threads, one (b,j) per thread; last block combines
// the 21 per-block partials in fixed order (bitwise deterministic).
__global__ __launch_bounds__(MSE_THREADS) void sdl_mse_kernel(
    const float* __restrict__ gt,   // [B,J]
    float* __restrict__ out)
{
    const int t = threadIdx.x;
    const int i = blockIdx.x * MSE_THREADS + t;

    const float4* gp = (const float4*)g_partial;
    float4 v = __ldcg(gp + i);
    float m = fminf(fminf(v.x, v.y), fminf(v.z, v.w));
    m = fmaxf(m, 0.0f);
    float d = sqrtf(m) - gt[i];
    float s = d * d;

    // Fixed-order intra-block reduction.
    s += __shfl_xor_sync(0xFFFFFFFFu, s, 16);
    s += __shfl_xor_sync(0xFFFFFFFFu, s, 8);
    s += __shfl_xor_sync(0xFFFFFFFFu, s, 4);
    s += __shfl_xor_sync(0xFFFFFFFFu, s, 2);
    s += __shfl_xor_sync(0xFFFFFFFFu, s, 1);
    __shared__ float ssum[MSE_THREADS / 32];
    const int w = t >> 5, l = t & 31;
    if (l == 0) ssum[w] = s;
    __syncthreads();
    if (t == 0) {
        float tot = ssum[0];
#pragma unroll
        for (int wi = 1; wi < MSE_THREADS / 32; wi++) tot += ssum[wi];
        g_bsum[blockIdx.x] = tot;
    }

    // Last block combines.
    __threadfence();
    __syncthreads();
    __shared__ unsigned s_last;
    if (t == 0) {
        unsigned c = atomicAdd(&g_mse_count, 1u);
        s_last = (c == (unsigned)(MSE_BLOCKS - 1)) ? 1u : 0u;
    }
    __syncthreads();
    if (s_last == 0u) return;

    if (t == 0) {
        float tot = 0.0f;
#pragma unroll
        for (int k = 0; k < MSE_BLOCKS; k++) tot += __ldcg(&g_bsum[k]);
        out[0] = tot / (float)NBJ;
        g_mse_count = 0;   // reset for next graph replay
    }
}

extern "C" void kernel_launch(void* const* d_in, const int* in_sizes, int n_in,
                              void* d_out, int out_size) {
    (void)in_sizes; (void)n_in; (void)out_size;
    const float* pred = (const float*)d_in[0];   // [64,42,3]
    const float* pts  = (const float*)d_in[1];   // [64,16384,3]
    const float* gt   = (const float*)d_in[2];   // [64,42]
    float* out = (float*)d_out;

    sdl_min_kernel<<<GRID, THREADS>>>(pred, pts);
    sdl_mse_kernel<<<MSE_BLOCKS, MSE_THREADS>>>(gt, out);
}

// round 16
// speedup vs baseline: 1.3756x; 1.0965x over previous
#include <cuda_runtime.h>
#include <math.h>

// Problem constants
#define BB 64
#define JJ 42
#define PP 16384
#define JG 3            // joint groups
#define JT 14           // joints per group (JG*JT == JJ)
#define PC 4            // P chunks
#define PPB (PP/PC)     // 4096 points per block
#define THREADS 256
#define PPT (PPB/THREADS)   // 16 points per thread
#define NF4 (PPB*3/4)       // 3072 float4 staged per block (48KB)
#define NWARP (THREADS/32)
#define GRID (BB*JG*PC)     // 768 blocks
#define NBJ (BB*JJ)         // 2688

// Scratch: per-(b,j) partial min-squared-distance, one slot per P-chunk.
__device__ float g_partial[NBJ * PC];

// X-macro over the 14 joints: fully-scalar named variables (no arrays ->
// nothing for ptxas to demote to local memory).
#define FOR_J(X) X(0) X(1) X(2) X(3) X(4) X(5) X(6) X(7) X(8) X(9) X(10) X(11) X(12) X(13)

// No __launch_bounds__: R12's default-heuristic allocation is the proven best.
__global__ void sdl_min_kernel(
    const float* __restrict__ pred,   // [B,J,3]
    const float* __restrict__ pts)    // [B,P,3]
{
    __shared__ float4 s_tile[NF4];    // 48KB staged point tile

    const int blk = blockIdx.x;
    const int pc = blk % PC;
    const int jg = (blk / PC) % JG;
    const int b  = blk / (PC * JG);
    const int t  = threadIdx.x;

    // ---- Stage: perfectly coalesced LDG.128 (nL=4/warp-op, 3x fewer wavefronts) ----
    const float4* src = (const float4*)(pts + ((size_t)b * PP + (size_t)pc * PPB) * 3);
#pragma unroll 3
    for (int k = 0; k < NF4 / THREADS; k++)
        s_tile[k * THREADS + t] = src[k * THREADS + t];

    const float* jp = pred + (size_t)(b * JJ + jg * JT) * 3;

#define DECL(n) float mx##n, my##n, mz##n, acc##n;
    FOR_J(DECL)
#undef DECL

#define INIT(n) { float ax = jp[3*n+0], ay = jp[3*n+1], az = jp[3*n+2]; \
                  mx##n = -2.0f*ax; my##n = -2.0f*ay; mz##n = -2.0f*az; \
                  acc##n = 3.0e38f; }
    FOR_J(INIT)
#undef INIT

    __syncthreads();

    // ---- Main loop: LDS.128 at 48B lane stride (bank-conflict-free) ----
#pragma unroll 1
    for (int it = 0; it < PPT / 4; it++) {
        const int base = (it * THREADS + t) * 3;
        float4 A  = s_tile[base + 0];
        float4 Bv = s_tile[base + 1];
        float4 C  = s_tile[base + 2];

#pragma unroll
        for (int q = 0; q < 4; q++) {
            float px, py, pz;
            if (q == 0)      { px = A.x;  py = A.y;  pz = A.z;  }
            else if (q == 1) { px = A.w;  py = Bv.x; pz = Bv.y; }
            else if (q == 2) { px = Bv.z; py = Bv.w; pz = C.x;  }
            else             { px = C.y;  py = C.z;  pz = C.w;  }
            float b2 = fmaf(pz, pz, fmaf(py, py, px * px));
#define UPD(n) { float tq = fmaf(mx##n, px, fmaf(my##n, py, fmaf(mz##n, pz, b2))); \
                 acc##n = fminf(acc##n, tq); }
            FOR_J(UPD)
#undef UPD
        }
    }

    // Epilogue: fold |a|^2, warp min-reduce, deposit in smem per joint.
    __shared__ float smin[NWARP][JT];
    const int w = t >> 5, l = t & 31;

#define FIN(n) { float ax = jp[3*n+0], ay = jp[3*n+1], az = jp[3*n+2]; \
                 float v = acc##n + fmaf(az, az, fmaf(ay, ay, ax*ax)); \
                 v = fminf(v, __shfl_xor_sync(0xFFFFFFFFu, v, 16)); \
                 v = fminf(v, __shfl_xor_sync(0xFFFFFFFFu, v, 8));  \
                 v = fminf(v, __shfl_xor_sync(0xFFFFFFFFu, v, 4));  \
                 v = fminf(v, __shfl_xor_sync(0xFFFFFFFFu, v, 2));  \
                 v = fminf(v, __shfl_xor_sync(0xFFFFFFFFu, v, 1));  \
                 if (l == 0) smin[w][n] = v; }
    FOR_J(FIN)
#undef FIN

    __syncthreads();

    if (t < JT) {
        float v = smin[0][t];
#pragma unroll
        for (int wi = 1; wi < NWARP; wi++) v = fminf(v, smin[wi][t]);
        g_partial[(size_t)(b * JJ + jg * JT + t) * PC + pc] = v;
    }
}

// Finalize: single block, 1024 threads (R12's proven version).
__global__ __launch_bounds__(1024) void sdl_mse_kernel(
    const float* __restrict__ gt,   // [B,J]
    float* __restrict__ out)
{
    const int t = threadIdx.x;
    float s = 0.0f;
    const float4* gp = (const float4*)g_partial;
#pragma unroll
    for (int k = 0; k < 3; k++) {
        int i = t + k * 1024;
        if (i < NBJ) {
            float4 v = __ldcg(gp + i);
            float m = fminf(fminf(v.x, v.y), fminf(v.z, v.w));
            m = fmaxf(m, 0.0f);
            float d = sqrtf(m) - gt[i];
            s = fmaf(d, d, s);
        }
    }
    s += __shfl_xor_sync(0xFFFFFFFFu, s, 16);
    s += __shfl_xor_sync(0xFFFFFFFFu, s, 8);
    s += __shfl_xor_sync(0xFFFFFFFFu, s, 4);
    s += __shfl_xor_sync(0xFFFFFFFFu, s, 2);
    s += __shfl_xor_sync(0xFFFFFFFFu, s, 1);
    __shared__ float ssum[32];
    const int w = t >> 5, l = t & 31;
    if (l == 0) ssum[w] = s;
    __syncthreads();
    if (t == 0) {
        float tot = ssum[0];
#pragma unroll
        for (int wi = 1; wi < 32; wi++) tot += ssum[wi];
        out[0] = tot / (float)NBJ;
    }
}

extern "C" void kernel_launch(void* const* d_in, const int* in_sizes, int n_in,
                              void* d_out, int out_size) {
    (void)in_sizes; (void)n_in; (void)out_size;
    const float* pred = (const float*)d_in[0];   // [64,42,3]
    const float* pts  = (const float*)d_in[1];   // [64,16384,3]
    const float* gt   = (const float*)d_in[2];   // [64,42]
    float* out = (float*)d_out;

    sdl_min_kernel<<<GRID, THREADS>>>(pred, pts);
    sdl_mse_kernel<<<1, 1024>>>(gt, out);
}